// round 1
// baseline (speedup 1.0000x reference)
#include <cuda_runtime.h>
#include <math.h>

#define Hdim 128
#define Wdim 128
#define Cdim 128
#define NPIX (Hdim * Wdim)          // 16384
#define HEADS 4
#define HD 32
#define KW 7
#define KK 49
#define RPBW 13                      // 2K-1
#define QSCALE 0.17677669529663689f  // 32^-0.5

// ---------------- scratch (no allocations allowed) ----------------
__device__ float g_xn [NPIX * Cdim];       // LN output (reused for LN2)
__device__ float g_qv [NPIX * 2 * Cdim];   // q (scaled) | v
__device__ float g_k  [NPIX * Cdim];
__device__ float g_att[NPIX * Cdim];
__device__ float g_x2 [NPIX * Cdim];       // x + proj(attn)
__device__ float g_h  [NPIX * 4 * Cdim];   // MLP hidden

// ---------------- LayerNorm: one block (128 thr) per pixel ----------------
__global__ void ln_kernel(const float* __restrict__ x,
                          const float* __restrict__ w,
                          const float* __restrict__ b,
                          float* __restrict__ out)
{
    int row = blockIdx.x;
    int tid = threadIdx.x;
    float v = x[row * Cdim + tid];
    float s = v, s2 = v * v;
    #pragma unroll
    for (int o = 16; o; o >>= 1) {
        s  += __shfl_xor_sync(0xffffffffu, s,  o);
        s2 += __shfl_xor_sync(0xffffffffu, s2, o);
    }
    __shared__ float ss[4], ss2[4];
    if ((tid & 31) == 0) { ss[tid >> 5] = s; ss2[tid >> 5] = s2; }
    __syncthreads();
    s  = ss[0] + ss[1] + ss[2] + ss[3];
    s2 = ss2[0] + ss2[1] + ss2[2] + ss2[3];
    float mu  = s * (1.0f / Cdim);
    float var = s2 * (1.0f / Cdim) - mu * mu;
    out[row * Cdim + tid] = (v - mu) * rsqrtf(var + 1e-5f) * w[tid] + b[tid];
}

// ---------------- GEMM: C[M,N] = A[M,K] @ W[N,K]^T (+ epilogue) ------------
// 64x64 block tile, BK=16, 256 threads, 4x4 per thread.
#define EPI_BIAS 0   // + bias
#define EPI_QV   1   // + bias, cols<128 scaled by QSCALE
#define EPI_RES  2   // + bias + res[row*N+col]
#define EPI_GELU 3   // gelu(acc + bias)
#define EPI_RES2 4   // + bias + res (final output)

template <int EPI>
__global__ void gemm64(const float* __restrict__ A,
                       const float* __restrict__ W,
                       const float* __restrict__ bias,
                       const float* __restrict__ res,
                       float* __restrict__ Cout,
                       int M, int N, int K)
{
    __shared__ float As[64][17];
    __shared__ float Ws[64][17];
    const int bn = blockIdx.x, bm = blockIdx.y;
    const int tid = threadIdx.x;
    const int tx = tid & 15, ty = tid >> 4;

    const int lr = tid >> 2;          // load row 0..63
    const int lc = (tid & 3) * 4;     // load col 0..12 step 4

    float acc[4][4] = {};

    for (int k0 = 0; k0 < K; k0 += 16) {
        float4 a4 = *(const float4*)&A[(size_t)(bm * 64 + lr) * K + k0 + lc];
        float4 w4 = *(const float4*)&W[(size_t)(bn * 64 + lr) * K + k0 + lc];
        As[lr][lc + 0] = a4.x; As[lr][lc + 1] = a4.y;
        As[lr][lc + 2] = a4.z; As[lr][lc + 3] = a4.w;
        Ws[lr][lc + 0] = w4.x; Ws[lr][lc + 1] = w4.y;
        Ws[lr][lc + 2] = w4.z; Ws[lr][lc + 3] = w4.w;
        __syncthreads();
        #pragma unroll
        for (int kk = 0; kk < 16; kk++) {
            float ra[4], rw[4];
            #pragma unroll
            for (int m = 0; m < 4; m++) ra[m] = As[ty * 4 + m][kk];
            #pragma unroll
            for (int n = 0; n < 4; n++) rw[n] = Ws[tx * 4 + n][kk];
            #pragma unroll
            for (int m = 0; m < 4; m++)
                #pragma unroll
                for (int n = 0; n < 4; n++)
                    acc[m][n] = fmaf(ra[m], rw[n], acc[m][n]);
        }
        __syncthreads();
    }

    #pragma unroll
    for (int m = 0; m < 4; m++) {
        int row = bm * 64 + ty * 4 + m;
        #pragma unroll
        for (int n = 0; n < 4; n++) {
            int col = bn * 64 + tx * 4 + n;
            float v = acc[m][n] + bias[col];
            if (EPI == EPI_QV) { if (col < Cdim) v *= QSCALE; }
            if (EPI == EPI_RES || EPI == EPI_RES2) v += res[(size_t)row * N + col];
            if (EPI == EPI_GELU) v = 0.5f * v * (1.0f + erff(v * 0.70710678118654752f));
            Cout[(size_t)row * N + col] = v;
        }
    }
}

// ---------------- neighborhood attention: 1 block / pixel, warp / head -----
__global__ void attn_kernel(const float* __restrict__ qv,
                            const float* __restrict__ kbuf,
                            const float* __restrict__ rpb,
                            float* __restrict__ out)
{
    const int pix = blockIdx.x;
    const int h = pix >> 7, w = pix & 127;
    const int tid = threadIdx.x;
    const int lane = tid & 31, hd = tid >> 5;

    __shared__ float q_s[Cdim];
    __shared__ int   nbr_s[KK];
    __shared__ float l_s[HEADS][56];

    q_s[tid] = qv[(size_t)pix * 256 + tid];   // q already scaled

    const int sh = min(max(h - 3, 0), Hdim - KW);
    const int sw = min(max(w - 3, 0), Wdim - KW);
    if (tid < KK) {
        int a = tid / KW, c = tid % KW;
        nbr_s[tid] = ((sh + a) << 7) + (sw + c);
    }
    __syncthreads();

    const float qme = q_s[hd * 32 + lane];

    // logits: one warp-reduced dot per neighbor
    for (int n = 0; n < KK; n++) {
        int np = nbr_s[n];
        float prod = qme * kbuf[(size_t)np * Cdim + hd * 32 + lane];
        #pragma unroll
        for (int o = 16; o; o >>= 1) prod += __shfl_xor_sync(0xffffffffu, prod, o);
        if (lane == 0) {
            int a = n / KW, c = n % KW;
            int rh  = sh + a - h + (KW - 1);
            int rw2 = sw + c - w + (KW - 1);
            l_s[hd][n] = prod + rpb[hd * (RPBW * RPBW) + rh * RPBW + rw2];
        }
    }
    __syncwarp();

    // softmax over 49 (2 values/lane)
    float l1 = l_s[hd][lane];
    float l2 = (lane + 32 < KK) ? l_s[hd][lane + 32] : -1e30f;
    float mx = fmaxf(l1, l2);
    #pragma unroll
    for (int o = 16; o; o >>= 1) mx = fmaxf(mx, __shfl_xor_sync(0xffffffffu, mx, o));
    float e1 = __expf(l1 - mx);
    float e2 = (lane + 32 < KK) ? __expf(l2 - mx) : 0.0f;
    float s = e1 + e2;
    #pragma unroll
    for (int o = 16; o; o >>= 1) s += __shfl_xor_sync(0xffffffffu, s, o);
    float inv = __fdividef(1.0f, s);
    l_s[hd][lane] = e1 * inv;
    if (lane + 32 < KK) l_s[hd][lane + 32] = e2 * inv;
    __syncwarp();

    // out = attn @ v_nbr   (lane = head dim, coalesced v reads)
    float acc = 0.0f;
    for (int n = 0; n < KK; n++) {
        acc = fmaf(l_s[hd][n], qv[(size_t)nbr_s[n] * 256 + Cdim + hd * 32 + lane], acc);
    }
    out[(size_t)pix * Cdim + tid] = acc;
}

// ---------------- launch -----------------
extern "C" void kernel_launch(void* const* d_in, const int* in_sizes, int n_in,
                              void* d_out, int out_size)
{
    const float* x      = (const float*)d_in[0];
    const float* y      = (const float*)d_in[1];
    const float* qv_w   = (const float*)d_in[2];
    const float* qv_b   = (const float*)d_in[3];
    const float* k_w    = (const float*)d_in[4];
    const float* k_b    = (const float*)d_in[5];
    const float* rpb    = (const float*)d_in[6];
    const float* proj_w = (const float*)d_in[7];
    const float* proj_b = (const float*)d_in[8];
    const float* n1_w   = (const float*)d_in[9];
    const float* n1_b   = (const float*)d_in[10];
    const float* n2_w   = (const float*)d_in[11];
    const float* n2_b   = (const float*)d_in[12];
    const float* fc1_w  = (const float*)d_in[13];
    const float* fc1_b  = (const float*)d_in[14];
    const float* fc2_w  = (const float*)d_in[15];
    const float* fc2_b  = (const float*)d_in[16];
    float* out = (float*)d_out;

    float *p_xn, *p_qv, *p_k, *p_att, *p_x2, *p_h;
    cudaGetSymbolAddress((void**)&p_xn,  g_xn);
    cudaGetSymbolAddress((void**)&p_qv,  g_qv);
    cudaGetSymbolAddress((void**)&p_k,   g_k);
    cudaGetSymbolAddress((void**)&p_att, g_att);
    cudaGetSymbolAddress((void**)&p_x2,  g_x2);
    cudaGetSymbolAddress((void**)&p_h,   g_h);

    const int M = NPIX;

    // 1) xn = LN1(x)
    ln_kernel<<<NPIX, 128>>>(x, n1_w, n1_b, p_xn);

    // 2) qv = xn @ qv_w^T + b  (q pre-scaled by HD^-0.5)
    gemm64<EPI_QV><<<dim3(4, M / 64), 256>>>(p_xn, qv_w, qv_b, nullptr, p_qv, M, 256, 128);

    // 3) k = y @ k_w^T + b
    gemm64<EPI_BIAS><<<dim3(2, M / 64), 256>>>(y, k_w, k_b, nullptr, p_k, M, 128, 128);

    // 4) neighborhood attention
    attn_kernel<<<NPIX, 128>>>(p_qv, p_k, rpb, p_att);

    // 5) x2 = x + attn @ proj_w^T + b
    gemm64<EPI_RES><<<dim3(2, M / 64), 256>>>(p_att, proj_w, proj_b, x, p_x2, M, 128, 128);

    // 6) xn = LN2(x2)
    ln_kernel<<<NPIX, 128>>>(p_x2, n2_w, n2_b, p_xn);

    // 7) h = gelu(xn @ fc1_w^T + b)
    gemm64<EPI_GELU><<<dim3(8, M / 64), 256>>>(p_xn, fc1_w, fc1_b, nullptr, p_h, M, 512, 128);

    // 8) out = x2 + h @ fc2_w^T + b
    gemm64<EPI_RES2><<<dim3(2, M / 64), 256>>>(p_h, fc2_w, fc2_b, p_x2, out, M, 128, 512);
}

// round 2
// speedup vs baseline: 1.7992x; 1.7992x over previous
#include <cuda_runtime.h>
#include <math.h>

#define Hdim 128
#define Wdim 128
#define Cdim 128
#define NPIX (Hdim * Wdim)          // 16384
#define HEADS 4
#define HD 32
#define KW 7
#define KK 49
#define RPBW 13                      // 2K-1
#define QSCALE 0.17677669529663689f  // 32^-0.5

// ---------------- scratch (no allocations allowed) ----------------
__device__ float g_xn [NPIX * Cdim];       // LN output (reused for LN2)
__device__ float g_qv [NPIX * 2 * Cdim];   // q (scaled) | v
__device__ float g_k  [NPIX * Cdim];
__device__ float g_att[NPIX * Cdim];
__device__ float g_x2 [NPIX * Cdim];       // x + proj(attn)
__device__ float g_h  [NPIX * 4 * Cdim];   // MLP hidden

// ---------------- LayerNorm: one block (128 thr) per pixel ----------------
__global__ void ln_kernel(const float* __restrict__ x,
                          const float* __restrict__ w,
                          const float* __restrict__ b,
                          float* __restrict__ out)
{
    int row = blockIdx.x;
    int tid = threadIdx.x;
    float v = x[row * Cdim + tid];
    float s = v, s2 = v * v;
    #pragma unroll
    for (int o = 16; o; o >>= 1) {
        s  += __shfl_xor_sync(0xffffffffu, s,  o);
        s2 += __shfl_xor_sync(0xffffffffu, s2, o);
    }
    __shared__ float ss[4], ss2[4];
    if ((tid & 31) == 0) { ss[tid >> 5] = s; ss2[tid >> 5] = s2; }
    __syncthreads();
    s  = ss[0] + ss[1] + ss[2] + ss[3];
    s2 = ss2[0] + ss2[1] + ss2[2] + ss2[3];
    float mu  = s * (1.0f / Cdim);
    float var = s2 * (1.0f / Cdim) - mu * mu;
    out[row * Cdim + tid] = (v - mu) * rsqrtf(var + 1e-5f) * w[tid] + b[tid];
}

// ---------------- GEMM: C[M,N] = A[M,K] @ W[N,K]^T (+ epilogue) ------------
// 128x128 block tile, BK=16, 256 threads, 8x8 per thread (2x2 quadrants of 4x4),
// double-buffered smem with transposed-K layout for conflict-free LDS.128.
#define EPI_BIAS 0   // + bias
#define EPI_QV   1   // + bias, cols<128 scaled by QSCALE
#define EPI_RES  2   // + bias + res[row*N+col]
#define EPI_GELU 3   // gelu(acc + bias)
#define EPI_RES2 4   // + bias + res (final output)

#define FMA44(ACC, A4, W4)                                        \
    ACC[0][0] = fmaf(A4.x, W4.x, ACC[0][0]);                      \
    ACC[0][1] = fmaf(A4.x, W4.y, ACC[0][1]);                      \
    ACC[0][2] = fmaf(A4.x, W4.z, ACC[0][2]);                      \
    ACC[0][3] = fmaf(A4.x, W4.w, ACC[0][3]);                      \
    ACC[1][0] = fmaf(A4.y, W4.x, ACC[1][0]);                      \
    ACC[1][1] = fmaf(A4.y, W4.y, ACC[1][1]);                      \
    ACC[1][2] = fmaf(A4.y, W4.z, ACC[1][2]);                      \
    ACC[1][3] = fmaf(A4.y, W4.w, ACC[1][3]);                      \
    ACC[2][0] = fmaf(A4.z, W4.x, ACC[2][0]);                      \
    ACC[2][1] = fmaf(A4.z, W4.y, ACC[2][1]);                      \
    ACC[2][2] = fmaf(A4.z, W4.z, ACC[2][2]);                      \
    ACC[2][3] = fmaf(A4.z, W4.w, ACC[2][3]);                      \
    ACC[3][0] = fmaf(A4.w, W4.x, ACC[3][0]);                      \
    ACC[3][1] = fmaf(A4.w, W4.y, ACC[3][1]);                      \
    ACC[3][2] = fmaf(A4.w, W4.z, ACC[3][2]);                      \
    ACC[3][3] = fmaf(A4.w, W4.w, ACC[3][3]);

template <int EPI>
__global__ __launch_bounds__(256, 2)
void gemm128(const float* __restrict__ A,
             const float* __restrict__ W,
             const float* __restrict__ bias,
             const float* __restrict__ res,
             float* __restrict__ Cout,
             int M, int N, int K)
{
    __shared__ float As[2][16][132];
    __shared__ float Ws[2][16][132];
    const int bn = blockIdx.x, bm = blockIdx.y;
    const int tid = threadIdx.x;
    const int tx = tid & 15, ty = tid >> 4;
    const int lrow = tid >> 1;         // 0..127
    const int cb   = (tid & 1) * 8;    // k-col base 0 or 8

    const float* Ap = A + (size_t)(bm * 128 + lrow) * K + cb;
    const float* Wp = W + (size_t)(bn * 128 + lrow) * K + cb;

    float4 pa0 = *(const float4*)(Ap);
    float4 pa1 = *(const float4*)(Ap + 4);
    float4 pw0 = *(const float4*)(Wp);
    float4 pw1 = *(const float4*)(Wp + 4);

    float acc[2][2][4][4] = {};

    const int nk = K >> 4;
    for (int s = 0; s < nk; s++) {
        const int b = s & 1;
        // store prefetched stage (transposed: smem[kk][row])
        As[b][cb + 0][lrow] = pa0.x; As[b][cb + 1][lrow] = pa0.y;
        As[b][cb + 2][lrow] = pa0.z; As[b][cb + 3][lrow] = pa0.w;
        As[b][cb + 4][lrow] = pa1.x; As[b][cb + 5][lrow] = pa1.y;
        As[b][cb + 6][lrow] = pa1.z; As[b][cb + 7][lrow] = pa1.w;
        Ws[b][cb + 0][lrow] = pw0.x; Ws[b][cb + 1][lrow] = pw0.y;
        Ws[b][cb + 2][lrow] = pw0.z; Ws[b][cb + 3][lrow] = pw0.w;
        Ws[b][cb + 4][lrow] = pw1.x; Ws[b][cb + 5][lrow] = pw1.y;
        Ws[b][cb + 6][lrow] = pw1.z; Ws[b][cb + 7][lrow] = pw1.w;
        __syncthreads();

        if (s + 1 < nk) {
            const float* Ap2 = Ap + (s + 1) * 16;
            const float* Wp2 = Wp + (s + 1) * 16;
            pa0 = *(const float4*)(Ap2);
            pa1 = *(const float4*)(Ap2 + 4);
            pw0 = *(const float4*)(Wp2);
            pw1 = *(const float4*)(Wp2 + 4);
        }

        #pragma unroll
        for (int kk = 0; kk < 16; kk++) {
            float4 a0 = *(const float4*)&As[b][kk][ty * 4];
            float4 a1 = *(const float4*)&As[b][kk][64 + ty * 4];
            float4 w0 = *(const float4*)&Ws[b][kk][tx * 4];
            float4 w1 = *(const float4*)&Ws[b][kk][64 + tx * 4];
            FMA44(acc[0][0], a0, w0);
            FMA44(acc[0][1], a0, w1);
            FMA44(acc[1][0], a1, w0);
            FMA44(acc[1][1], a1, w1);
        }
        // next iteration stores into the other buffer; single sync/iter is safe
    }

    #pragma unroll
    for (int qm = 0; qm < 2; qm++) {
        #pragma unroll
        for (int qn = 0; qn < 2; qn++) {
            const int colb = bn * 128 + qn * 64 + tx * 4;
            float4 bi = *(const float4*)&bias[colb];
            #pragma unroll
            for (int m = 0; m < 4; m++) {
                const int row = bm * 128 + qm * 64 + ty * 4 + m;
                float4 v;
                v.x = acc[qm][qn][m][0] + bi.x;
                v.y = acc[qm][qn][m][1] + bi.y;
                v.z = acc[qm][qn][m][2] + bi.z;
                v.w = acc[qm][qn][m][3] + bi.w;
                if (EPI == EPI_QV) {
                    if (colb < Cdim) { v.x *= QSCALE; v.y *= QSCALE; v.z *= QSCALE; v.w *= QSCALE; }
                }
                if (EPI == EPI_RES || EPI == EPI_RES2) {
                    float4 r = *(const float4*)&res[(size_t)row * N + colb];
                    v.x += r.x; v.y += r.y; v.z += r.z; v.w += r.w;
                }
                if (EPI == EPI_GELU) {
                    v.x = 0.5f * v.x * (1.0f + erff(v.x * 0.70710678118654752f));
                    v.y = 0.5f * v.y * (1.0f + erff(v.y * 0.70710678118654752f));
                    v.z = 0.5f * v.z * (1.0f + erff(v.z * 0.70710678118654752f));
                    v.w = 0.5f * v.w * (1.0f + erff(v.w * 0.70710678118654752f));
                }
                *(float4*)&Cout[(size_t)row * N + colb] = v;
            }
        }
    }
}

// ---------------- neighborhood attention: block = 8x8 pixel tile x 1 head --
// Stage 14x14 k-neighborhood (head slice) in smem, thread = pixel, q in regs,
// serial float4 dots; then restage v into the same buffer for the output pass.
__global__ __launch_bounds__(64)
void attn_kernel(const float* __restrict__ qv,
                 const float* __restrict__ kbuf,
                 const float* __restrict__ rpb,
                 float* __restrict__ out)
{
    __shared__ __align__(16) float kv_s[196 * 36];   // 14x14 rows x 32ch (pad 36)
    __shared__ float ls[KK * 64];                    // logits/probs per pixel
    __shared__ float rpb_s[RPBW * RPBW];

    const int hd = blockIdx.z;
    const int bh = blockIdx.y * 8, bw = blockIdx.x * 8;
    const int tid = threadIdx.x;
    const int py = tid >> 3, px = tid & 7;
    const int h = bh + py, w = bw + px;
    const int o_h = min(max(bh - 3, 0), Hdim - 14);
    const int o_w = min(max(bw - 3, 0), Wdim - 14);

    for (int i = tid; i < RPBW * RPBW; i += 64) rpb_s[i] = rpb[hd * RPBW * RPBW + i];

    // stage k neighborhood (196 rows x 8 float4)
    for (int idx = tid; idx < 196 * 8; idx += 64) {
        int rr = idx >> 3, j = idx & 7;
        int gh = o_h + rr / 14, gw = o_w + rr % 14;
        ((float4*)&kv_s[rr * 36])[j] =
            ((const float4*)&kbuf[(size_t)(gh * Wdim + gw) * Cdim + hd * HD])[j];
    }
    __syncthreads();

    // q (pre-scaled) in registers
    float4 qf[8];
    {
        const float4* qp = (const float4*)&qv[(size_t)(h * Wdim + w) * 256 + hd * HD];
        #pragma unroll
        for (int j = 0; j < 8; j++) qf[j] = qp[j];
    }

    const int sh = min(max(h - 3, 0), Hdim - KW);
    const int sw = min(max(w - 3, 0), Wdim - KW);
    const int lr0 = sh - o_h, lc0 = sw - o_w;
    const int rh0 = sh - h + 6, rw0 = sw - w + 6;

    // logits
    for (int a = 0; a < KW; a++) {
        for (int c = 0; c < KW; c++) {
            const float4* kp = (const float4*)&kv_s[((lr0 + a) * 14 + lc0 + c) * 36];
            float d = 0.0f;
            #pragma unroll
            for (int j = 0; j < 8; j++) {
                float4 k4 = kp[j];
                d = fmaf(qf[j].x, k4.x, d);
                d = fmaf(qf[j].y, k4.y, d);
                d = fmaf(qf[j].z, k4.z, d);
                d = fmaf(qf[j].w, k4.w, d);
            }
            ls[(a * KW + c) * 64 + tid] = d + rpb_s[(rh0 + a) * RPBW + rw0 + c];
        }
    }

    // softmax (per-thread serial over its 49 smem slots)
    float mx = -1e30f;
    for (int n = 0; n < KK; n++) mx = fmaxf(mx, ls[n * 64 + tid]);
    float ssum = 0.0f;
    for (int n = 0; n < KK; n++) {
        float e = __expf(ls[n * 64 + tid] - mx);
        ls[n * 64 + tid] = e;
        ssum += e;
    }
    const float inv = __fdividef(1.0f, ssum);
    __syncthreads();   // everyone done reading k before restaging v

    // stage v neighborhood into the same buffer
    for (int idx = tid; idx < 196 * 8; idx += 64) {
        int rr = idx >> 3, j = idx & 7;
        int gh = o_h + rr / 14, gw = o_w + rr % 14;
        ((float4*)&kv_s[rr * 36])[j] =
            ((const float4*)&qv[(size_t)(gh * Wdim + gw) * 256 + Cdim + hd * HD])[j];
    }
    __syncthreads();

    // out = probs @ v
    float4 acc[8];
    #pragma unroll
    for (int j = 0; j < 8; j++) acc[j] = make_float4(0.f, 0.f, 0.f, 0.f);
    for (int a = 0; a < KW; a++) {
        for (int c = 0; c < KW; c++) {
            float p = ls[(a * KW + c) * 64 + tid] * inv;
            const float4* vp = (const float4*)&kv_s[((lr0 + a) * 14 + lc0 + c) * 36];
            #pragma unroll
            for (int j = 0; j < 8; j++) {
                float4 v4 = vp[j];
                acc[j].x = fmaf(p, v4.x, acc[j].x);
                acc[j].y = fmaf(p, v4.y, acc[j].y);
                acc[j].z = fmaf(p, v4.z, acc[j].z);
                acc[j].w = fmaf(p, v4.w, acc[j].w);
            }
        }
    }
    float4* op = (float4*)&out[(size_t)(h * Wdim + w) * Cdim + hd * HD];
    #pragma unroll
    for (int j = 0; j < 8; j++) op[j] = acc[j];
}

// ---------------- launch -----------------
extern "C" void kernel_launch(void* const* d_in, const int* in_sizes, int n_in,
                              void* d_out, int out_size)
{
    const float* x      = (const float*)d_in[0];
    const float* y      = (const float*)d_in[1];
    const float* qv_w   = (const float*)d_in[2];
    const float* qv_b   = (const float*)d_in[3];
    const float* k_w    = (const float*)d_in[4];
    const float* k_b    = (const float*)d_in[5];
    const float* rpb    = (const float*)d_in[6];
    const float* proj_w = (const float*)d_in[7];
    const float* proj_b = (const float*)d_in[8];
    const float* n1_w   = (const float*)d_in[9];
    const float* n1_b   = (const float*)d_in[10];
    const float* n2_w   = (const float*)d_in[11];
    const float* n2_b   = (const float*)d_in[12];
    const float* fc1_w  = (const float*)d_in[13];
    const float* fc1_b  = (const float*)d_in[14];
    const float* fc2_w  = (const float*)d_in[15];
    const float* fc2_b  = (const float*)d_in[16];
    float* out = (float*)d_out;

    float *p_xn, *p_qv, *p_k, *p_att, *p_x2, *p_h;
    cudaGetSymbolAddress((void**)&p_xn,  g_xn);
    cudaGetSymbolAddress((void**)&p_qv,  g_qv);
    cudaGetSymbolAddress((void**)&p_k,   g_k);
    cudaGetSymbolAddress((void**)&p_att, g_att);
    cudaGetSymbolAddress((void**)&p_x2,  g_x2);
    cudaGetSymbolAddress((void**)&p_h,   g_h);

    const int M = NPIX;

    // 1) xn = LN1(x)
    ln_kernel<<<NPIX, 128>>>(x, n1_w, n1_b, p_xn);

    // 2) qv = xn @ qv_w^T + b  (q pre-scaled by HD^-0.5)
    gemm128<EPI_QV><<<dim3(2, M / 128), 256>>>(p_xn, qv_w, qv_b, nullptr, p_qv, M, 256, 128);

    // 3) k = y @ k_w^T + b
    gemm128<EPI_BIAS><<<dim3(1, M / 128), 256>>>(y, k_w, k_b, nullptr, p_k, M, 128, 128);

    // 4) neighborhood attention (8x8 tile per block, 1 head per block.z)
    attn_kernel<<<dim3(Wdim / 8, Hdim / 8, HEADS), 64>>>(p_qv, p_k, rpb, p_att);

    // 5) x2 = x + attn @ proj_w^T + b
    gemm128<EPI_RES><<<dim3(1, M / 128), 256>>>(p_att, proj_w, proj_b, x, p_x2, M, 128, 128);

    // 6) xn = LN2(x2)
    ln_kernel<<<NPIX, 128>>>(p_x2, n2_w, n2_b, p_xn);

    // 7) h = gelu(xn @ fc1_w^T + b)
    gemm128<EPI_GELU><<<dim3(4, M / 128), 256>>>(p_xn, fc1_w, fc1_b, nullptr, p_h, M, 512, 128);

    // 8) out = x2 + h @ fc2_w^T + b
    gemm128<EPI_RES2><<<dim3(1, M / 128), 256>>>(p_h, fc2_w, fc2_b, p_x2, out, M, 128, 512);
}

// round 4
// speedup vs baseline: 1.9794x; 1.1002x over previous
#include <cuda_runtime.h>
#include <cuda_bf16.h>
#include <math.h>
#include <stdint.h>

#define Hdim 128
#define Wdim 128
#define Cdim 128
#define NPIX (Hdim * Wdim)          // 16384
#define HEADS 4
#define HD 32
#define KW 7
#define KK 49
#define RPBW 13
#define QSCALE 0.17677669529663689f

// ---------------- scratch ----------------
__device__ float g_qv [NPIX * 256];               // q(scaled)|v  fp32
__device__ float g_k  [NPIX * Cdim];              // k fp32
__device__ float g_x2 [NPIX * Cdim];              // x + proj(attn) fp32
__device__ __nv_bfloat16 s_xn_hi[NPIX * Cdim];
__device__ __nv_bfloat16 s_xn_lo[NPIX * Cdim];
__device__ __nv_bfloat16 s_y_hi [NPIX * Cdim];
__device__ __nv_bfloat16 s_y_lo [NPIX * Cdim];
__device__ __nv_bfloat16 s_att_hi[NPIX * Cdim];
__device__ __nv_bfloat16 s_att_lo[NPIX * Cdim];
__device__ __nv_bfloat16 s_h_hi [NPIX * 512];
__device__ __nv_bfloat16 s_h_lo [NPIX * 512];
// weights split, packed: qv@0 (32768), k@32768, proj@49152, fc1@65536, fc2@131072
__device__ __nv_bfloat16 s_w_hi[196608];
__device__ __nv_bfloat16 s_w_lo[196608];

// ---------------- helpers ----------------
__device__ __forceinline__ uint32_t smem_u32(const void* p) {
    uint32_t a;
    asm("{ .reg .u64 t; cvta.to.shared.u64 t, %1; cvt.u32.u64 %0, t; }" : "=r"(a) : "l"(p));
    return a;
}
__device__ __forceinline__ void ldm_x4(uint32_t& r0, uint32_t& r1, uint32_t& r2, uint32_t& r3,
                                       uint32_t addr) {
    asm volatile("ldmatrix.sync.aligned.m8n8.x4.shared.b16 {%0,%1,%2,%3}, [%4];"
        : "=r"(r0), "=r"(r1), "=r"(r2), "=r"(r3) : "r"(addr));
}
__device__ __forceinline__ void mma_bf16(float* d, const uint32_t* a, const uint32_t* b) {
    asm volatile("mma.sync.aligned.m16n8k16.row.col.f32.bf16.bf16.f32 "
        "{%0,%1,%2,%3}, {%4,%5,%6,%7}, {%8,%9}, {%0,%1,%2,%3};"
        : "+f"(d[0]), "+f"(d[1]), "+f"(d[2]), "+f"(d[3])
        : "r"(a[0]), "r"(a[1]), "r"(a[2]), "r"(a[3]), "r"(b[0]), "r"(b[1]));
}
__device__ __forceinline__ void splitf(float a, __nv_bfloat16& h, __nv_bfloat16& l) {
    h = __float2bfloat16(a);
    l = __float2bfloat16(a - __bfloat162float(h));
}

// ---------------- prep: split y + all weights into hi/lo bf16 --------------
__global__ void split_kernel(const float* __restrict__ y,
                             const float* __restrict__ qvw, const float* __restrict__ kw,
                             const float* __restrict__ pw,  const float* __restrict__ f1,
                             const float* __restrict__ f2,
                             __nv_bfloat16* __restrict__ yh, __nv_bfloat16* __restrict__ yl,
                             __nv_bfloat16* __restrict__ wh, __nv_bfloat16* __restrict__ wl)
{
    int i = blockIdx.x * 256 + threadIdx.x;
    const int NY = NPIX * Cdim;
    if (i < NY) { splitf(y[i], yh[i], yl[i]); return; }
    int wi = i - NY;
    if (wi >= 196608) return;
    float v;
    if      (wi < 32768)  v = qvw[wi];
    else if (wi < 49152)  v = kw [wi - 32768];
    else if (wi < 65536)  v = pw [wi - 49152];
    else if (wi < 131072) v = f1 [wi - 65536];
    else                  v = f2 [wi - 131072];
    splitf(v, wh[wi], wl[wi]);
}

// ---------------- LayerNorm -> hi/lo bf16 ----------------
__global__ void ln_kernel(const float* __restrict__ x,
                          const float* __restrict__ w,
                          const float* __restrict__ b,
                          __nv_bfloat16* __restrict__ oh,
                          __nv_bfloat16* __restrict__ ol)
{
    int row = blockIdx.x;
    int tid = threadIdx.x;
    float v = x[row * Cdim + tid];
    float s = v, s2 = v * v;
    #pragma unroll
    for (int o = 16; o; o >>= 1) {
        s  += __shfl_xor_sync(0xffffffffu, s,  o);
        s2 += __shfl_xor_sync(0xffffffffu, s2, o);
    }
    __shared__ float ss[4], ss2[4];
    if ((tid & 31) == 0) { ss[tid >> 5] = s; ss2[tid >> 5] = s2; }
    __syncthreads();
    s  = ss[0] + ss[1] + ss[2] + ss[3];
    s2 = ss2[0] + ss2[1] + ss2[2] + ss2[3];
    float mu  = s * (1.0f / Cdim);
    float var = s2 * (1.0f / Cdim) - mu * mu;
    float r = (v - mu) * rsqrtf(var + 1e-5f) * w[tid] + b[tid];
    splitf(r, oh[row * Cdim + tid], ol[row * Cdim + tid]);
}

// ---------------- split-bf16 GEMM via mma.sync (legacy HMMA) ---------------
// D[128x128] per CTA = A[M,K] @ W[N,K]^T. 8 warps in 4(M)x2(N); warp = 32x64.
// K staged in 64-wide chunks; 4 bf16 smem buffers (Ah,Al,Wh,Wl), pitch 72.
#define EPI_BIAS 0
#define EPI_QV   1
#define EPI_RES  2
#define EPI_GELU 3
#define EPI_RES2 4

#define PITCH 72
#define BUFB (128 * PITCH * 2)       // 18432 bytes per buffer
#define GSMEM (4 * BUFB)             // 73728

template <int EPI, int KTOT>
__global__ __launch_bounds__(256, 2)
void gemm_mma(const __nv_bfloat16* __restrict__ Ahi, const __nv_bfloat16* __restrict__ Alo,
              const __nv_bfloat16* __restrict__ Whi, const __nv_bfloat16* __restrict__ Wlo,
              const float* __restrict__ bias, const float* __restrict__ res,
              float* __restrict__ outf,
              __nv_bfloat16* __restrict__ oh, __nv_bfloat16* __restrict__ ol,
              int out_ld)
{
    extern __shared__ __align__(16) char dsm[];
    const uint32_t sb = smem_u32(dsm);
    const uint32_t sAh = sb, sAl = sb + BUFB, sWh = sb + 2 * BUFB, sWl = sb + 3 * BUFB;

    const int tid = threadIdx.x, lane = tid & 31, wid = tid >> 5;
    const int wm = wid & 3, wn = wid >> 2;        // warp 32 rows x 64 cols
    const int bn = blockIdx.x, bm = blockIdx.y;

    float acc[2][8][4];
    #pragma unroll
    for (int i = 0; i < 2; i++)
        #pragma unroll
        for (int j = 0; j < 8; j++)
            #pragma unroll
            for (int q = 0; q < 4; q++) acc[i][j][q] = 0.0f;

    // fragment smem addresses (byte): row*144 + k*2
    const uint32_t aRow = wm * 32 + (lane & 15);
    const uint32_t aKof = ((lane >> 4) << 3);
    const uint32_t bRow = wn * 64 + ((lane >> 4) << 3) + (lane & 7);
    const uint32_t bKof = ((lane >> 3) & 1) << 3;

    for (int kb = 0; kb < KTOT; kb += 64) {
        // ---- stage chunk: 2048 uint4 tasks (A:0-1023, W:1024-2047), hi+lo --
        #pragma unroll
        for (int t = tid; t < 2048; t += 256) {
            const int isW = t >> 10;
            const int u = t & 1023;
            const int row = u >> 3, c8 = u & 7;
            const size_t gi = (size_t)((isW ? bn : bm) * 128 + row) * KTOT + kb + c8 * 8;
            const uint4 h4 = *(const uint4*)((isW ? Whi : Ahi) + gi);
            const uint4 l4 = *(const uint4*)((isW ? Wlo : Alo) + gi);
            char* p = dsm + (isW ? 2 * BUFB : 0) + row * (PITCH * 2) + c8 * 16;
            *(uint4*)p = h4;
            *(uint4*)(p + BUFB) = l4;
        }
        __syncthreads();

        #pragma unroll
        for (int ks = 0; ks < 4; ks++) {
            const uint32_t aoff = (aRow * PITCH + ks * 16 + aKof) * 2;
            uint32_t ah0[4], ah1[4], al0[4], al1[4];
            ldm_x4(ah0[0], ah0[1], ah0[2], ah0[3], sAh + aoff);
            ldm_x4(ah1[0], ah1[1], ah1[2], ah1[3], sAh + aoff + 16 * PITCH * 2);
            ldm_x4(al0[0], al0[1], al0[2], al0[3], sAl + aoff);
            ldm_x4(al1[0], al1[1], al1[2], al1[3], sAl + aoff + 16 * PITCH * 2);

            #pragma unroll
            for (int nf2 = 0; nf2 < 4; nf2++) {
                const uint32_t boff = ((bRow + nf2 * 16) * PITCH + ks * 16 + bKof) * 2;
                uint32_t bh[4], bl[4];
                ldm_x4(bh[0], bh[1], bh[2], bh[3], sWh + boff);
                ldm_x4(bl[0], bl[1], bl[2], bl[3], sWl + boff);
                const int n0 = nf2 * 2;
                mma_bf16(acc[0][n0],     ah0, bh);
                mma_bf16(acc[0][n0],     ah0, bl);
                mma_bf16(acc[0][n0],     al0, bh);
                mma_bf16(acc[0][n0 + 1], ah0, bh + 2);
                mma_bf16(acc[0][n0 + 1], ah0, bl + 2);
                mma_bf16(acc[0][n0 + 1], al0, bh + 2);
                mma_bf16(acc[1][n0],     ah1, bh);
                mma_bf16(acc[1][n0],     ah1, bl);
                mma_bf16(acc[1][n0],     al1, bh);
                mma_bf16(acc[1][n0 + 1], ah1, bh + 2);
                mma_bf16(acc[1][n0 + 1], ah1, bl + 2);
                mma_bf16(acc[1][n0 + 1], al1, bh + 2);
            }
        }
        __syncthreads();
    }

    // ---- epilogue: direct float2 stores ----
    #pragma unroll
    for (int mf = 0; mf < 2; mf++) {
        const int row0 = bm * 128 + wm * 32 + mf * 16 + (lane >> 2);
        #pragma unroll
        for (int nf = 0; nf < 8; nf++) {
            const int col = bn * 128 + wn * 64 + nf * 8 + (lane & 3) * 2;
            float2 bi = *(const float2*)&bias[col];
            float v[4];
            v[0] = acc[mf][nf][0] + bi.x;
            v[1] = acc[mf][nf][1] + bi.y;
            v[2] = acc[mf][nf][2] + bi.x;
            v[3] = acc[mf][nf][3] + bi.y;
            if (EPI == EPI_QV) {
                if (col < Cdim) { v[0] *= QSCALE; v[1] *= QSCALE; v[2] *= QSCALE; v[3] *= QSCALE; }
            }
            if (EPI == EPI_RES || EPI == EPI_RES2) {
                float2 r0 = *(const float2*)&res[(size_t)row0 * out_ld + col];
                float2 r1 = *(const float2*)&res[(size_t)(row0 + 8) * out_ld + col];
                v[0] += r0.x; v[1] += r0.y; v[2] += r1.x; v[3] += r1.y;
            }
            if (EPI == EPI_GELU) {
                #pragma unroll
                for (int q = 0; q < 4; q++)
                    v[q] = 0.5f * v[q] * (1.0f + erff(v[q] * 0.70710678118654752f));
                const size_t o0 = (size_t)row0 * out_ld + col;
                const size_t o1 = (size_t)(row0 + 8) * out_ld + col;
                __nv_bfloat16 h, l;
                splitf(v[0], h, l); oh[o0]     = h; ol[o0]     = l;
                splitf(v[1], h, l); oh[o0 + 1] = h; ol[o0 + 1] = l;
                splitf(v[2], h, l); oh[o1]     = h; ol[o1]     = l;
                splitf(v[3], h, l); oh[o1 + 1] = h; ol[o1 + 1] = l;
            } else {
                *(float2*)&outf[(size_t)row0 * out_ld + col]       = make_float2(v[0], v[1]);
                *(float2*)&outf[(size_t)(row0 + 8) * out_ld + col] = make_float2(v[2], v[3]);
            }
        }
    }
}

// ---------------- neighborhood attention (probs in registers) --------------
__global__ __launch_bounds__(64)
void attn_kernel(const float* __restrict__ qv,
                 const float* __restrict__ kbuf,
                 const float* __restrict__ rpb,
                 __nv_bfloat16* __restrict__ oh,
                 __nv_bfloat16* __restrict__ ol)
{
    __shared__ __align__(16) float kv_s[196 * 36];
    __shared__ float rpb_s[RPBW * RPBW];

    const int hd = blockIdx.z;
    const int bh = blockIdx.y * 8, bw = blockIdx.x * 8;
    const int tid = threadIdx.x;
    const int py = tid >> 3, px = tid & 7;
    const int h = bh + py, w = bw + px;
    const int o_h = min(max(bh - 3, 0), Hdim - 14);
    const int o_w = min(max(bw - 3, 0), Wdim - 14);

    for (int i = tid; i < RPBW * RPBW; i += 64) rpb_s[i] = rpb[hd * RPBW * RPBW + i];

    for (int idx = tid; idx < 196 * 8; idx += 64) {
        int rr = idx >> 3, j = idx & 7;
        int gh = o_h + rr / 14, gw = o_w + rr % 14;
        ((float4*)&kv_s[rr * 36])[j] =
            ((const float4*)&kbuf[(size_t)(gh * Wdim + gw) * Cdim + hd * HD])[j];
    }
    __syncthreads();

    float4 qf[8];
    {
        const float4* qp = (const float4*)&qv[(size_t)(h * Wdim + w) * 256 + hd * HD];
        #pragma unroll
        for (int j = 0; j < 8; j++) qf[j] = qp[j];
    }

    const int sh = min(max(h - 3, 0), Hdim - KW);
    const int sw = min(max(w - 3, 0), Wdim - KW);
    const int lr0 = sh - o_h, lc0 = sw - o_w;
    const int rh0 = sh - h + 6, rw0 = sw - w + 6;

    float p[KK];
    #pragma unroll
    for (int a = 0; a < KW; a++) {
        #pragma unroll
        for (int c = 0; c < KW; c++) {
            const float4* kp = (const float4*)&kv_s[((lr0 + a) * 14 + lc0 + c) * 36];
            float d = 0.0f;
            #pragma unroll
            for (int j = 0; j < 8; j++) {
                float4 k4 = kp[j];
                d = fmaf(qf[j].x, k4.x, d);
                d = fmaf(qf[j].y, k4.y, d);
                d = fmaf(qf[j].z, k4.z, d);
                d = fmaf(qf[j].w, k4.w, d);
            }
            p[a * KW + c] = d + rpb_s[(rh0 + a) * RPBW + rw0 + c];
        }
    }

    float mx = -1e30f;
    #pragma unroll
    for (int n = 0; n < KK; n++) mx = fmaxf(mx, p[n]);
    float ssum = 0.0f;
    #pragma unroll
    for (int n = 0; n < KK; n++) { p[n] = __expf(p[n] - mx); ssum += p[n]; }
    const float inv = __fdividef(1.0f, ssum);
    __syncthreads();

    for (int idx = tid; idx < 196 * 8; idx += 64) {
        int rr = idx >> 3, j = idx & 7;
        int gh = o_h + rr / 14, gw = o_w + rr % 14;
        ((float4*)&kv_s[rr * 36])[j] =
            ((const float4*)&qv[(size_t)(gh * Wdim + gw) * 256 + Cdim + hd * HD])[j];
    }
    __syncthreads();

    float4 acc[8];
    #pragma unroll
    for (int j = 0; j < 8; j++) acc[j] = make_float4(0.f, 0.f, 0.f, 0.f);
    #pragma unroll
    for (int a = 0; a < KW; a++) {
        #pragma unroll
        for (int c = 0; c < KW; c++) {
            float pr = p[a * KW + c] * inv;
            const float4* vp = (const float4*)&kv_s[((lr0 + a) * 14 + lc0 + c) * 36];
            #pragma unroll
            for (int j = 0; j < 8; j++) {
                float4 v4 = vp[j];
                acc[j].x = fmaf(pr, v4.x, acc[j].x);
                acc[j].y = fmaf(pr, v4.y, acc[j].y);
                acc[j].z = fmaf(pr, v4.z, acc[j].z);
                acc[j].w = fmaf(pr, v4.w, acc[j].w);
            }
        }
    }
    const size_t base = (size_t)(h * Wdim + w) * Cdim + hd * HD;
    #pragma unroll
    for (int j = 0; j < 8; j++) {
        __nv_bfloat16 hh, ll;
        splitf(acc[j].x, hh, ll); oh[base + j*4 + 0] = hh; ol[base + j*4 + 0] = ll;
        splitf(acc[j].y, hh, ll); oh[base + j*4 + 1] = hh; ol[base + j*4 + 1] = ll;
        splitf(acc[j].z, hh, ll); oh[base + j*4 + 2] = hh; ol[base + j*4 + 2] = ll;
        splitf(acc[j].w, hh, ll); oh[base + j*4 + 3] = hh; ol[base + j*4 + 3] = ll;
    }
}

// ---------------- launch -----------------
extern "C" void kernel_launch(void* const* d_in, const int* in_sizes, int n_in,
                              void* d_out, int out_size)
{
    const float* x      = (const float*)d_in[0];
    const float* y      = (const float*)d_in[1];
    const float* qv_w   = (const float*)d_in[2];
    const float* qv_b   = (const float*)d_in[3];
    const float* k_w    = (const float*)d_in[4];
    const float* k_b    = (const float*)d_in[5];
    const float* rpb    = (const float*)d_in[6];
    const float* proj_w = (const float*)d_in[7];
    const float* proj_b = (const float*)d_in[8];
    const float* n1_w   = (const float*)d_in[9];
    const float* n1_b   = (const float*)d_in[10];
    const float* n2_w   = (const float*)d_in[11];
    const float* n2_b   = (const float*)d_in[12];
    const float* fc1_w  = (const float*)d_in[13];
    const float* fc1_b  = (const float*)d_in[14];
    const float* fc2_w  = (const float*)d_in[15];
    const float* fc2_b  = (const float*)d_in[16];
    float* out = (float*)d_out;

    float *p_qv, *p_k, *p_x2;
    __nv_bfloat16 *xnh, *xnl, *yh, *yl, *ath, *atl, *hh, *hl, *wh, *wl;
    cudaGetSymbolAddress((void**)&p_qv, g_qv);
    cudaGetSymbolAddress((void**)&p_k,  g_k);
    cudaGetSymbolAddress((void**)&p_x2, g_x2);
    cudaGetSymbolAddress((void**)&xnh, s_xn_hi);
    cudaGetSymbolAddress((void**)&xnl, s_xn_lo);
    cudaGetSymbolAddress((void**)&yh,  s_y_hi);
    cudaGetSymbolAddress((void**)&yl,  s_y_lo);
    cudaGetSymbolAddress((void**)&ath, s_att_hi);
    cudaGetSymbolAddress((void**)&atl, s_att_lo);
    cudaGetSymbolAddress((void**)&hh,  s_h_hi);
    cudaGetSymbolAddress((void**)&hl,  s_h_lo);
    cudaGetSymbolAddress((void**)&wh,  s_w_hi);
    cudaGetSymbolAddress((void**)&wl,  s_w_lo);

    cudaFuncSetAttribute(gemm_mma<EPI_QV,128>,   cudaFuncAttributeMaxDynamicSharedMemorySize, GSMEM);
    cudaFuncSetAttribute(gemm_mma<EPI_BIAS,128>, cudaFuncAttributeMaxDynamicSharedMemorySize, GSMEM);
    cudaFuncSetAttribute(gemm_mma<EPI_RES,128>,  cudaFuncAttributeMaxDynamicSharedMemorySize, GSMEM);
    cudaFuncSetAttribute(gemm_mma<EPI_GELU,128>, cudaFuncAttributeMaxDynamicSharedMemorySize, GSMEM);
    cudaFuncSetAttribute(gemm_mma<EPI_RES2,512>, cudaFuncAttributeMaxDynamicSharedMemorySize, GSMEM);

    // 0) split y + weights
    split_kernel<<<(NPIX * Cdim + 196608 + 255) / 256, 256>>>(
        y, qv_w, k_w, proj_w, fc1_w, fc2_w, yh, yl, wh, wl);

    // 1) xn = LN1(x) -> hi/lo
    ln_kernel<<<NPIX, 128>>>(x, n1_w, n1_b, xnh, xnl);

    // 2) qv = xn @ qv_w^T + b (q scaled)
    gemm_mma<EPI_QV,128><<<dim3(2, NPIX / 128), 256, GSMEM>>>(
        xnh, xnl, wh + 0, wl + 0, qv_b, nullptr, p_qv, nullptr, nullptr, 256);

    // 3) k = y @ k_w^T + b
    gemm_mma<EPI_BIAS,128><<<dim3(1, NPIX / 128), 256, GSMEM>>>(
        yh, yl, wh + 32768, wl + 32768, k_b, nullptr, p_k, nullptr, nullptr, 128);

    // 4) neighborhood attention -> hi/lo
    attn_kernel<<<dim3(Wdim / 8, Hdim / 8, HEADS), 64>>>(p_qv, p_k, rpb, ath, atl);

    // 5) x2 = x + att @ proj_w^T + b
    gemm_mma<EPI_RES,128><<<dim3(1, NPIX / 128), 256, GSMEM>>>(
        ath, atl, wh + 49152, wl + 49152, proj_b, x, p_x2, nullptr, nullptr, 128);

    // 6) xn = LN2(x2) -> hi/lo
    ln_kernel<<<NPIX, 128>>>(p_x2, n2_w, n2_b, xnh, xnl);

    // 7) h = gelu(xn @ fc1_w^T + b) -> hi/lo
    gemm_mma<EPI_GELU,128><<<dim3(4, NPIX / 128), 256, GSMEM>>>(
        xnh, xnl, wh + 65536, wl + 65536, fc1_b, nullptr, nullptr, hh, hl, 512);

    // 8) out = x2 + h @ fc2_w^T + b
    gemm_mma<EPI_RES2,512><<<dim3(1, NPIX / 128), 256, GSMEM>>>(
        hh, hl, wh + 131072, wl + 131072, fc2_b, p_x2, out, nullptr, nullptr, 128);
}

// round 5
// speedup vs baseline: 2.0371x; 1.0291x over previous
#include <cuda_runtime.h>
#include <cuda_bf16.h>
#include <math.h>
#include <stdint.h>

#define Hdim 128
#define Wdim 128
#define Cdim 128
#define NPIX (Hdim * Wdim)
#define HEADS 4
#define HD 32
#define KW 7
#define KK 49
#define RPBW 13
#define QSCALE 0.17677669529663689f

// ---------------- scratch ----------------
__device__ float g_qv [NPIX * 256];
__device__ float g_k  [NPIX * Cdim];
__device__ float g_x2 [NPIX * Cdim];
__device__ __nv_bfloat16 s_xn_hi[NPIX * Cdim];
__device__ __nv_bfloat16 s_xn_lo[NPIX * Cdim];
__device__ __nv_bfloat16 s_y_hi [NPIX * Cdim];
__device__ __nv_bfloat16 s_y_lo [NPIX * Cdim];
__device__ __nv_bfloat16 s_att_hi[NPIX * Cdim];
__device__ __nv_bfloat16 s_att_lo[NPIX * Cdim];
__device__ __nv_bfloat16 s_h_hi [NPIX * 512];
__device__ __nv_bfloat16 s_h_lo [NPIX * 512];
__device__ __nv_bfloat16 s_w_hi[196608];
__device__ __nv_bfloat16 s_w_lo[196608];

// ---------------- helpers ----------------
__device__ __forceinline__ uint32_t smem_u32(const void* p) {
    uint32_t a;
    asm("{ .reg .u64 t; cvta.to.shared.u64 t, %1; cvt.u32.u64 %0, t; }" : "=r"(a) : "l"(p));
    return a;
}
__device__ __forceinline__ void ldm_x4(uint32_t& r0, uint32_t& r1, uint32_t& r2, uint32_t& r3,
                                       uint32_t addr) {
    asm volatile("ldmatrix.sync.aligned.m8n8.x4.shared.b16 {%0,%1,%2,%3}, [%4];"
        : "=r"(r0), "=r"(r1), "=r"(r2), "=r"(r3) : "r"(addr));
}
__device__ __forceinline__ void mma_bf16(float* d, const uint32_t* a, const uint32_t* b) {
    asm volatile("mma.sync.aligned.m16n8k16.row.col.f32.bf16.bf16.f32 "
        "{%0,%1,%2,%3}, {%4,%5,%6,%7}, {%8,%9}, {%0,%1,%2,%3};"
        : "+f"(d[0]), "+f"(d[1]), "+f"(d[2]), "+f"(d[3])
        : "r"(a[0]), "r"(a[1]), "r"(a[2]), "r"(a[3]), "r"(b[0]), "r"(b[1]));
}
__device__ __forceinline__ void cp16(uint32_t dst, const void* src) {
    asm volatile("cp.async.ca.shared.global [%0], [%1], 16;" :: "r"(dst), "l"(src));
}
#define CP_COMMIT() asm volatile("cp.async.commit_group;" ::: "memory")
#define CP_WAIT(n)  asm volatile("cp.async.wait_group %0;" :: "n"(n) : "memory")
__device__ __forceinline__ void splitf(float a, __nv_bfloat16& h, __nv_bfloat16& l) {
    h = __float2bfloat16(a);
    l = __float2bfloat16(a - __bfloat162float(h));
}

// ---------------- prep: split y + all weights ----------------
__global__ void split_kernel(const float* __restrict__ y,
                             const float* __restrict__ qvw, const float* __restrict__ kw,
                             const float* __restrict__ pw,  const float* __restrict__ f1,
                             const float* __restrict__ f2,
                             __nv_bfloat16* __restrict__ yh, __nv_bfloat16* __restrict__ yl,
                             __nv_bfloat16* __restrict__ wh, __nv_bfloat16* __restrict__ wl)
{
    int i = blockIdx.x * 256 + threadIdx.x;
    const int NY = NPIX * Cdim;
    if (i < NY) { splitf(y[i], yh[i], yl[i]); return; }
    int wi = i - NY;
    if (wi >= 196608) return;
    float v;
    if      (wi < 32768)  v = qvw[wi];
    else if (wi < 49152)  v = kw [wi - 32768];
    else if (wi < 65536)  v = pw [wi - 49152];
    else if (wi < 131072) v = f1 [wi - 65536];
    else                  v = f2 [wi - 131072];
    splitf(v, wh[wi], wl[wi]);
}

// ---------------- LayerNorm -> hi/lo bf16 ----------------
__global__ void ln_kernel(const float* __restrict__ x,
                          const float* __restrict__ w,
                          const float* __restrict__ b,
                          __nv_bfloat16* __restrict__ oh,
                          __nv_bfloat16* __restrict__ ol)
{
    int row = blockIdx.x;
    int tid = threadIdx.x;
    float v = x[row * Cdim + tid];
    float s = v, s2 = v * v;
    #pragma unroll
    for (int o = 16; o; o >>= 1) {
        s  += __shfl_xor_sync(0xffffffffu, s,  o);
        s2 += __shfl_xor_sync(0xffffffffu, s2, o);
    }
    __shared__ float ss[4], ss2[4];
    if ((tid & 31) == 0) { ss[tid >> 5] = s; ss2[tid >> 5] = s2; }
    __syncthreads();
    s  = ss[0] + ss[1] + ss[2] + ss[3];
    s2 = ss2[0] + ss2[1] + ss2[2] + ss2[3];
    float mu  = s * (1.0f / Cdim);
    float var = s2 * (1.0f / Cdim) - mu * mu;
    float r = (v - mu) * rsqrtf(var + 1e-5f) * w[tid] + b[tid];
    splitf(r, oh[row * Cdim + tid], ol[row * Cdim + tid]);
}

// ------------- split-bf16 GEMM, 64x128 tile, cp.async double-buffered ------
#define EPI_BIAS 0
#define EPI_QV   1
#define EPI_RES  2
#define EPI_GELU 3
#define EPI_RES2 4

#define PITCH 72                      // bf16 elems; 144 bytes per row
#define OFF_AL 9216                   // 64*144
#define OFF_WH 18432
#define OFF_WL 36864
#define STAGE  55296                  // OFF_WH + 2*128*144
#define GSMEM  (2 * STAGE)

template <int EPI, int KTOT>
__global__ __launch_bounds__(256, 2)
void gemm_mma(const __nv_bfloat16* __restrict__ Ahi, const __nv_bfloat16* __restrict__ Alo,
              const __nv_bfloat16* __restrict__ Whi, const __nv_bfloat16* __restrict__ Wlo,
              const float* __restrict__ bias, const float* __restrict__ res,
              float* __restrict__ outf,
              __nv_bfloat16* __restrict__ oh, __nv_bfloat16* __restrict__ ol,
              int out_ld)
{
    extern __shared__ __align__(16) char dsm[];
    const uint32_t sb = smem_u32(dsm);
    const int tid = threadIdx.x, lane = tid & 31, wid = tid >> 5;
    const int wm = wid & 3, wn = wid >> 2;        // warp = 16 rows x 64 cols
    const int bn = blockIdx.x, bm = blockIdx.y;

    // staging task precompute (12 tasks/thread)
    // t<512 Ah | <1024 Al | <2048 Wh | <3072 Wl
    const int nch = KTOT / 64;

    float acc[8][4];
    #pragma unroll
    for (int j = 0; j < 8; j++)
        #pragma unroll
        for (int q = 0; q < 4; q++) acc[j][q] = 0.0f;

    const uint32_t aRow = wm * 16 + (lane & 15);
    const uint32_t aKof = ((lane >> 4) << 3);
    const uint32_t bRow = wn * 64 + ((lane >> 4) << 3) + (lane & 7);
    const uint32_t bKof = ((lane >> 3) & 1) << 3;

    // ---- issue stage 0 ----
    #pragma unroll
    for (int t = tid; t < 3072; t += 256) {
        const int sel = t >> 10;             // 0: A(hi/lo), 1: Wh, 2: Wl
        uint32_t dst; const __nv_bfloat16* src;
        if (sel == 0) {
            const int isLo = (t >> 9) & 1;
            const int u = t & 511, row = u >> 3, c8 = u & 7;
            dst = sb + (isLo ? OFF_AL : 0) + row * 144 + c8 * 16;
            src = (isLo ? Alo : Ahi) + (size_t)(bm * 64 + row) * KTOT + c8 * 8;
        } else {
            const int u = t & 1023, row = u >> 3, c8 = u & 7;
            dst = sb + (sel == 1 ? OFF_WH : OFF_WL) + row * 144 + c8 * 16;
            src = (sel == 1 ? Whi : Wlo) + (size_t)(bn * 128 + row) * KTOT + c8 * 8;
        }
        cp16(dst, src);
    }
    CP_COMMIT();

    for (int ch = 0; ch < nch; ch++) {
        if (ch + 1 < nch) {
            const uint32_t st = sb + ((ch + 1) & 1) * STAGE;
            const int kb = (ch + 1) * 64;
            #pragma unroll
            for (int t = tid; t < 3072; t += 256) {
                const int sel = t >> 10;
                uint32_t dst; const __nv_bfloat16* src;
                if (sel == 0) {
                    const int isLo = (t >> 9) & 1;
                    const int u = t & 511, row = u >> 3, c8 = u & 7;
                    dst = st + (isLo ? OFF_AL : 0) + row * 144 + c8 * 16;
                    src = (isLo ? Alo : Ahi) + (size_t)(bm * 64 + row) * KTOT + kb + c8 * 8;
                } else {
                    const int u = t & 1023, row = u >> 3, c8 = u & 7;
                    dst = st + (sel == 1 ? OFF_WH : OFF_WL) + row * 144 + c8 * 16;
                    src = (sel == 1 ? Whi : Wlo) + (size_t)(bn * 128 + row) * KTOT + kb + c8 * 8;
                }
                cp16(dst, src);
            }
            CP_COMMIT();
            CP_WAIT(1);
        } else {
            CP_WAIT(0);
        }
        __syncthreads();

        const uint32_t st = sb + (ch & 1) * STAGE;
        #pragma unroll
        for (int ks = 0; ks < 4; ks++) {
            const uint32_t aoff = st + (aRow * PITCH + ks * 16 + aKof) * 2;
            uint32_t ah[4], al[4];
            ldm_x4(ah[0], ah[1], ah[2], ah[3], aoff);
            ldm_x4(al[0], al[1], al[2], al[3], aoff + OFF_AL);
            #pragma unroll
            for (int nf4 = 0; nf4 < 4; nf4++) {
                const uint32_t boff = st + OFF_WH +
                    ((bRow + nf4 * 16) * PITCH + ks * 16 + bKof) * 2;
                uint32_t bh[4], bl[4];
                ldm_x4(bh[0], bh[1], bh[2], bh[3], boff);
                ldm_x4(bl[0], bl[1], bl[2], bl[3], boff + 18432);
                const int n0 = nf4 * 2;
                mma_bf16(acc[n0],     ah, bh);
                mma_bf16(acc[n0 + 1], ah, bh + 2);
                mma_bf16(acc[n0],     ah, bl);
                mma_bf16(acc[n0 + 1], ah, bl + 2);
                mma_bf16(acc[n0],     al, bh);
                mma_bf16(acc[n0 + 1], al, bh + 2);
            }
        }
        __syncthreads();
    }

    // ---- epilogue ----
    const int row0 = bm * 64 + wm * 16 + (lane >> 2);
    #pragma unroll
    for (int nf = 0; nf < 8; nf++) {
        const int col = bn * 128 + wn * 64 + nf * 8 + (lane & 3) * 2;
        float2 bi = *(const float2*)&bias[col];
        float v[4];
        v[0] = acc[nf][0] + bi.x;
        v[1] = acc[nf][1] + bi.y;
        v[2] = acc[nf][2] + bi.x;
        v[3] = acc[nf][3] + bi.y;
        if (EPI == EPI_QV) {
            if (col < Cdim) { v[0] *= QSCALE; v[1] *= QSCALE; v[2] *= QSCALE; v[3] *= QSCALE; }
        }
        if (EPI == EPI_RES || EPI == EPI_RES2) {
            float2 r0 = *(const float2*)&res[(size_t)row0 * out_ld + col];
            float2 r1 = *(const float2*)&res[(size_t)(row0 + 8) * out_ld + col];
            v[0] += r0.x; v[1] += r0.y; v[2] += r1.x; v[3] += r1.y;
        }
        if (EPI == EPI_GELU) {
            #pragma unroll
            for (int q = 0; q < 4; q++)
                v[q] = 0.5f * v[q] * (1.0f + erff(v[q] * 0.70710678118654752f));
            const size_t o0 = (size_t)row0 * out_ld + col;
            const size_t o1 = (size_t)(row0 + 8) * out_ld + col;
            __nv_bfloat16 h, l;
            splitf(v[0], h, l); oh[o0]     = h; ol[o0]     = l;
            splitf(v[1], h, l); oh[o0 + 1] = h; ol[o0 + 1] = l;
            splitf(v[2], h, l); oh[o1]     = h; ol[o1]     = l;
            splitf(v[3], h, l); oh[o1 + 1] = h; ol[o1 + 1] = l;
        } else {
            *(float2*)&outf[(size_t)row0 * out_ld + col]       = make_float2(v[0], v[1]);
            *(float2*)&outf[(size_t)(row0 + 8) * out_ld + col] = make_float2(v[2], v[3]);
        }
    }
}

// ------- neighborhood attention: block = 16x8 pixel tile x 1 head ----------
#define NBW 22
#define NBH 14
#define NBR (NBW * NBH)   // 308

__global__ __launch_bounds__(128)
void attn_kernel(const float* __restrict__ qv,
                 const float* __restrict__ kbuf,
                 const float* __restrict__ rpb,
                 __nv_bfloat16* __restrict__ oh,
                 __nv_bfloat16* __restrict__ ol)
{
    __shared__ __align__(16) float kv_s[NBR * 36];   // 44352 B
    __shared__ float rpb_s[RPBW * RPBW];

    const int hd = blockIdx.z;
    const int bw = blockIdx.x * 16, bh = blockIdx.y * 8;
    const int tid = threadIdx.x;
    const int px = tid & 15, py = tid >> 4;
    const int h = bh + py, w = bw + px;
    const int o_h = min(max(bh - 3, 0), Hdim - NBH);
    const int o_w = min(max(bw - 3, 0), Wdim - NBW);

    for (int i = tid; i < RPBW * RPBW; i += 128) rpb_s[i] = rpb[hd * RPBW * RPBW + i];

    for (int idx = tid; idx < NBR * 8; idx += 128) {
        int rr = idx >> 3, j = idx & 7;
        int gh = o_h + rr / NBW, gw = o_w + rr % NBW;
        ((float4*)&kv_s[rr * 36])[j] =
            ((const float4*)&kbuf[(size_t)(gh * Wdim + gw) * Cdim + hd * HD])[j];
    }
    __syncthreads();

    float4 qf[8];
    {
        const float4* qp = (const float4*)&qv[(size_t)(h * Wdim + w) * 256 + hd * HD];
        #pragma unroll
        for (int j = 0; j < 8; j++) qf[j] = qp[j];
    }

    const int sh = min(max(h - 3, 0), Hdim - KW);
    const int sw = min(max(w - 3, 0), Wdim - KW);
    const int lr0 = sh - o_h, lc0 = sw - o_w;
    const int rh0 = sh - h + 6, rw0 = sw - w + 6;

    float p[KK];
    #pragma unroll
    for (int a = 0; a < KW; a++) {
        #pragma unroll
        for (int c = 0; c < KW; c++) {
            const float4* kp = (const float4*)&kv_s[((lr0 + a) * NBW + lc0 + c) * 36];
            float d = 0.0f;
            #pragma unroll
            for (int j = 0; j < 8; j++) {
                float4 k4 = kp[j];
                d = fmaf(qf[j].x, k4.x, d);
                d = fmaf(qf[j].y, k4.y, d);
                d = fmaf(qf[j].z, k4.z, d);
                d = fmaf(qf[j].w, k4.w, d);
            }
            p[a * KW + c] = d + rpb_s[(rh0 + a) * RPBW + rw0 + c];
        }
    }

    float mx = -1e30f;
    #pragma unroll
    for (int n = 0; n < KK; n++) mx = fmaxf(mx, p[n]);
    float ssum = 0.0f;
    #pragma unroll
    for (int n = 0; n < KK; n++) { p[n] = __expf(p[n] - mx); ssum += p[n]; }
    const float inv = __fdividef(1.0f, ssum);
    __syncthreads();

    for (int idx = tid; idx < NBR * 8; idx += 128) {
        int rr = idx >> 3, j = idx & 7;
        int gh = o_h + rr / NBW, gw = o_w + rr % NBW;
        ((float4*)&kv_s[rr * 36])[j] =
            ((const float4*)&qv[(size_t)(gh * Wdim + gw) * 256 + Cdim + hd * HD])[j];
    }
    __syncthreads();

    float4 acc[8];
    #pragma unroll
    for (int j = 0; j < 8; j++) acc[j] = make_float4(0.f, 0.f, 0.f, 0.f);
    #pragma unroll
    for (int a = 0; a < KW; a++) {
        #pragma unroll
        for (int c = 0; c < KW; c++) {
            float pr = p[a * KW + c] * inv;
            const float4* vp = (const float4*)&kv_s[((lr0 + a) * NBW + lc0 + c) * 36];
            #pragma unroll
            for (int j = 0; j < 8; j++) {
                float4 v4 = vp[j];
                acc[j].x = fmaf(pr, v4.x, acc[j].x);
                acc[j].y = fmaf(pr, v4.y, acc[j].y);
                acc[j].z = fmaf(pr, v4.z, acc[j].z);
                acc[j].w = fmaf(pr, v4.w, acc[j].w);
            }
        }
    }
    const size_t base = (size_t)(h * Wdim + w) * Cdim + hd * HD;
    #pragma unroll
    for (int j = 0; j < 8; j++) {
        __nv_bfloat16 hh, ll;
        splitf(acc[j].x, hh, ll); oh[base + j*4 + 0] = hh; ol[base + j*4 + 0] = ll;
        splitf(acc[j].y, hh, ll); oh[base + j*4 + 1] = hh; ol[base + j*4 + 1] = ll;
        splitf(acc[j].z, hh, ll); oh[base + j*4 + 2] = hh; ol[base + j*4 + 2] = ll;
        splitf(acc[j].w, hh, ll); oh[base + j*4 + 3] = hh; ol[base + j*4 + 3] = ll;
    }
}

// ---------------- launch -----------------
extern "C" void kernel_launch(void* const* d_in, const int* in_sizes, int n_in,
                              void* d_out, int out_size)
{
    const float* x      = (const float*)d_in[0];
    const float* y      = (const float*)d_in[1];
    const float* qv_w   = (const float*)d_in[2];
    const float* qv_b   = (const float*)d_in[3];
    const float* k_w    = (const float*)d_in[4];
    const float* k_b    = (const float*)d_in[5];
    const float* rpb    = (const float*)d_in[6];
    const float* proj_w = (const float*)d_in[7];
    const float* proj_b = (const float*)d_in[8];
    const float* n1_w   = (const float*)d_in[9];
    const float* n1_b   = (const float*)d_in[10];
    const float* n2_w   = (const float*)d_in[11];
    const float* n2_b   = (const float*)d_in[12];
    const float* fc1_w  = (const float*)d_in[13];
    const float* fc1_b  = (const float*)d_in[14];
    const float* fc2_w  = (const float*)d_in[15];
    const float* fc2_b  = (const float*)d_in[16];
    float* out = (float*)d_out;

    float *p_qv, *p_k, *p_x2;
    __nv_bfloat16 *xnh, *xnl, *yh, *yl, *ath, *atl, *hh, *hl, *wh, *wl;
    cudaGetSymbolAddress((void**)&p_qv, g_qv);
    cudaGetSymbolAddress((void**)&p_k,  g_k);
    cudaGetSymbolAddress((void**)&p_x2, g_x2);
    cudaGetSymbolAddress((void**)&xnh, s_xn_hi);
    cudaGetSymbolAddress((void**)&xnl, s_xn_lo);
    cudaGetSymbolAddress((void**)&yh,  s_y_hi);
    cudaGetSymbolAddress((void**)&yl,  s_y_lo);
    cudaGetSymbolAddress((void**)&ath, s_att_hi);
    cudaGetSymbolAddress((void**)&atl, s_att_lo);
    cudaGetSymbolAddress((void**)&hh,  s_h_hi);
    cudaGetSymbolAddress((void**)&hl,  s_h_lo);
    cudaGetSymbolAddress((void**)&wh,  s_w_hi);
    cudaGetSymbolAddress((void**)&wl,  s_w_lo);

    cudaFuncSetAttribute(gemm_mma<EPI_QV,128>,   cudaFuncAttributeMaxDynamicSharedMemorySize, GSMEM);
    cudaFuncSetAttribute(gemm_mma<EPI_BIAS,128>, cudaFuncAttributeMaxDynamicSharedMemorySize, GSMEM);
    cudaFuncSetAttribute(gemm_mma<EPI_RES,128>,  cudaFuncAttributeMaxDynamicSharedMemorySize, GSMEM);
    cudaFuncSetAttribute(gemm_mma<EPI_GELU,128>, cudaFuncAttributeMaxDynamicSharedMemorySize, GSMEM);
    cudaFuncSetAttribute(gemm_mma<EPI_RES2,512>, cudaFuncAttributeMaxDynamicSharedMemorySize, GSMEM);

    // 0) split y + weights
    split_kernel<<<(NPIX * Cdim + 196608 + 255) / 256, 256>>>(
        y, qv_w, k_w, proj_w, fc1_w, fc2_w, yh, yl, wh, wl);

    // 1) xn = LN1(x)
    ln_kernel<<<NPIX, 128>>>(x, n1_w, n1_b, xnh, xnl);

    // 2) qv = xn @ qv_w^T + b (q scaled)
    gemm_mma<EPI_QV,128><<<dim3(2, NPIX / 64), 256, GSMEM>>>(
        xnh, xnl, wh + 0, wl + 0, qv_b, nullptr, p_qv, nullptr, nullptr, 256);

    // 3) k = y @ k_w^T + b
    gemm_mma<EPI_BIAS,128><<<dim3(1, NPIX / 64), 256, GSMEM>>>(
        yh, yl, wh + 32768, wl + 32768, k_b, nullptr, p_k, nullptr, nullptr, 128);

    // 4) neighborhood attention
    attn_kernel<<<dim3(Wdim / 16, Hdim / 8, HEADS), 128>>>(p_qv, p_k, rpb, ath, atl);

    // 5) x2 = x + att @ proj_w^T + b
    gemm_mma<EPI_RES,128><<<dim3(1, NPIX / 64), 256, GSMEM>>>(
        ath, atl, wh + 49152, wl + 49152, proj_b, x, p_x2, nullptr, nullptr, 128);

    // 6) xn = LN2(x2)
    ln_kernel<<<NPIX, 128>>>(p_x2, n2_w, n2_b, xnh, xnl);

    // 7) h = gelu(xn @ fc1_w^T + b)
    gemm_mma<EPI_GELU,128><<<dim3(4, NPIX / 64), 256, GSMEM>>>(
        xnh, xnl, wh + 65536, wl + 65536, fc1_b, nullptr, nullptr, hh, hl, 512);

    // 8) out = x2 + h @ fc2_w^T + b
    gemm_mma<EPI_RES2,512><<<dim3(1, NPIX / 64), 256, GSMEM>>>(
        hh, hl, wh + 131072, wl + 131072, fc2_b, p_x2, out, nullptr, nullptr, 128);
}